// round 1
// baseline (speedup 1.0000x reference)
#include <cuda_runtime.h>
#include <cuda_bf16.h>

// Rule-indexed sparse graph convolution.
//   out[n,k,f] = sum_{e: src(e)=n} W[k, lab[src], lab[dst], prop(e)] * x[dst(e), f]
//              + b[k, lab[n], f]
//
// Strategy: build CSR (grouped by edge_src) each call into static __device__
// scratch (no allocations), precompute the 4 per-edge rule weights during the
// scatter pass, then a no-atomics gather pass: one 128-thread block per node,
// thread = feature f, 4 register accumulators (one per channel k).

#define KC 4
#define LC 50
#define PC 16
#define FC 128
#define NN 20000
#define EE 640000
#define LLP (LC * LC * PC)   // 40000, k-stride in Param_W

// ---------- static scratch (allocation-free) ----------
__device__ int    g_count[NN];
__device__ int    g_offset[NN + 1];
__device__ int    g_cursor[NN];
__device__ int    g_dst_sorted[EE];
__device__ float4 g_w_sorted[EE];

// ---------- phase 1: zero degree counts ----------
__global__ void k_zero_counts() {
    int i = blockIdx.x * blockDim.x + threadIdx.x;
    if (i < NN) g_count[i] = 0;
}

// ---------- phase 2: degree histogram over edge_src ----------
__global__ void k_hist(const int* __restrict__ edge_src, int E) {
    int e = blockIdx.x * blockDim.x + threadIdx.x;
    if (e < E) atomicAdd(&g_count[edge_src[e]], 1);
}

// ---------- phase 3: exclusive scan (single block) ----------
#define SCAN_T 1024
__global__ void k_scan() {
    __shared__ int sums[SCAN_T];
    int t = threadIdx.x;
    const int CH = (NN + SCAN_T - 1) / SCAN_T;   // 20
    int start = t * CH;
    int end   = start + CH; if (end > NN) end = NN;

    int s = 0;
    for (int i = start; i < end; ++i) s += g_count[i];
    sums[t] = s;
    __syncthreads();

    // Hillis-Steele inclusive scan over 1024 partials
    for (int off = 1; off < SCAN_T; off <<= 1) {
        int v = (t >= off) ? sums[t - off] : 0;
        __syncthreads();
        sums[t] += v;
        __syncthreads();
    }

    int run = (t == 0) ? 0 : sums[t - 1];
    for (int i = start; i < end; ++i) {
        int c = g_count[i];
        g_offset[i] = run;
        g_cursor[i] = run;
        run += c;
    }
    if (t == SCAN_T - 1) g_offset[NN] = run;
}

// ---------- phase 4: scatter edges into CSR slots + precompute weights ----------
__global__ void k_scatter(const int*   __restrict__ edge_src,
                          const int*   __restrict__ edge_dst,
                          const int*   __restrict__ edge_prop,
                          const int*   __restrict__ labels,
                          const float* __restrict__ Pw,
                          int E) {
    int e = blockIdx.x * blockDim.x + threadIdx.x;
    if (e >= E) return;
    int s  = edge_src[e];
    int d  = edge_dst[e];
    int p  = edge_prop[e];
    int lv = labels[s];
    int lw = labels[d];
    int base = (lv * LC + lw) * PC + p;   // k=0 index; k-stride = LLP
    float4 w;
    w.x = __ldg(&Pw[base]);
    w.y = __ldg(&Pw[base + LLP]);
    w.z = __ldg(&Pw[base + 2 * LLP]);
    w.w = __ldg(&Pw[base + 3 * LLP]);
    int pos = atomicAdd(&g_cursor[s], 1);
    g_dst_sorted[pos] = d;
    g_w_sorted[pos]   = w;
}

// ---------- phase 5: gather (no atomics), bias folded into epilogue ----------
__global__ void __launch_bounds__(FC)
k_gather(const float* __restrict__ x,
         const int*   __restrict__ labels,
         const float* __restrict__ Pb,
         float*       __restrict__ out) {
    int n = blockIdx.x;
    int f = threadIdx.x;            // 0..127
    int beg = g_offset[n];
    int end = g_offset[n + 1];

    float a0 = 0.f, a1 = 0.f, a2 = 0.f, a3 = 0.f;

    int i = beg;
    // 2-wide software pipeline for memory-level parallelism on the
    // dst -> x-row pointer chase.
    for (; i + 1 < end; i += 2) {
        int    d0 = g_dst_sorted[i];
        int    d1 = g_dst_sorted[i + 1];
        float4 w0 = g_w_sorted[i];
        float4 w1 = g_w_sorted[i + 1];
        float  x0 = __ldg(&x[d0 * FC + f]);
        float  x1 = __ldg(&x[d1 * FC + f]);
        a0 += w0.x * x0; a1 += w0.y * x0; a2 += w0.z * x0; a3 += w0.w * x0;
        a0 += w1.x * x1; a1 += w1.y * x1; a2 += w1.z * x1; a3 += w1.w * x1;
    }
    if (i < end) {
        int    d0 = g_dst_sorted[i];
        float4 w0 = g_w_sorted[i];
        float  x0 = __ldg(&x[d0 * FC + f]);
        a0 += w0.x * x0; a1 += w0.y * x0; a2 += w0.z * x0; a3 += w0.w * x0;
    }

    int lab = labels[n];
    const float* bb = Pb + lab * FC + f;   // + k*LC*FC per channel
    float* o = out + (size_t)n * (KC * FC) + f;
    o[0 * FC] = a0 + __ldg(&bb[0 * LC * FC]);
    o[1 * FC] = a1 + __ldg(&bb[1 * LC * FC]);
    o[2 * FC] = a2 + __ldg(&bb[2 * LC * FC]);
    o[3 * FC] = a3 + __ldg(&bb[3 * LC * FC]);
}

extern "C" void kernel_launch(void* const* d_in, const int* in_sizes, int n_in,
                              void* d_out, int out_size) {
    const float* x         = (const float*)d_in[0];
    const int*   labels    = (const int*)  d_in[1];
    const int*   edge_src  = (const int*)  d_in[2];
    const int*   edge_dst  = (const int*)  d_in[3];
    const int*   edge_prop = (const int*)  d_in[4];
    const float* Pw        = (const float*)d_in[5];
    const float* Pb        = (const float*)d_in[6];
    float*       out       = (float*)d_out;

    const int E = in_sizes[2];   // 640000
    (void)n_in; (void)out_size;

    k_zero_counts<<<(NN + 255) / 256, 256>>>();
    k_hist<<<(E + 255) / 256, 256>>>(edge_src, E);
    k_scan<<<1, SCAN_T>>>();
    k_scatter<<<(E + 255) / 256, 256>>>(edge_src, edge_dst, edge_prop,
                                        labels, Pw, E);
    k_gather<<<NN, FC>>>(x, labels, Pb, out);
}

// round 2
// speedup vs baseline: 2.0415x; 2.0415x over previous
#include <cuda_runtime.h>
#include <cuda_bf16.h>

// Rule-indexed sparse graph convolution, round 2.
//   out[n,k,f] = sum_{e: src(e)=n} W[k, lab[src], lab[dst], prop(e)] * x[dst(e), f]
//              + b[k, lab[n], f]
//
// Pipeline (3 launches):
//  1. k_init     : zero per-node cursors + transpose Param_W into float4 PwT
//  2. k_scatter  : bucket edges by src into fixed-capacity slots (packed d|p<<16)
//  3. k_gather   : warp-per-node, lane = float4 of features; weights computed
//                  in-gather via warp-broadcast loads; bias folded in epilogue.

#define KC 4
#define LC 50
#define PC 16
#define FC 128
#define NN 20000
#define EE 640000
#define LLP (LC * LC * PC)   // 40000, k-stride in Param_W
#define RULES (LC * LC * PC) // 40000 per k -> 160000/4... rule index space = L*L*P = 40000? no:
// rule index = (lv*L + lw)*P + p  in [0, L*L*P) = [0, 40000)
#define NRULE (LC * LC * PC) // 40000
#define CAP 128              // slots per node; Poisson(32) => overflow prob ~1e-35

// ---------- static scratch (allocation-free) ----------
__device__ int    g_cursor[NN];
__device__ int    g_slot[NN * CAP];        // 10.24 MB, packed d | (p<<16)
__device__ float4 g_PwT[NRULE];            // 640 KB: {w_k0, w_k1, w_k2, w_k3} per rule

// ---------- phase 1: zero cursors + transpose weights ----------
__global__ void k_init(const float* __restrict__ Pw) {
    int i = blockIdx.x * blockDim.x + threadIdx.x;
    if (i < NRULE) {
        float4 v;
        v.x = Pw[i];
        v.y = Pw[i + LLP];
        v.z = Pw[i + 2 * LLP];
        v.w = Pw[i + 3 * LLP];
        g_PwT[i] = v;
    }
    if (i < NN) g_cursor[i] = 0;
}

// ---------- phase 2: bucket edges by src (fixed capacity, no scan) ----------
__global__ void k_scatter(const int* __restrict__ edge_src,
                          const int* __restrict__ edge_dst,
                          const int* __restrict__ edge_prop,
                          int E) {
    int e = blockIdx.x * blockDim.x + threadIdx.x;
    if (e >= E) return;
    int s = edge_src[e];
    int d = edge_dst[e];
    int p = edge_prop[e];
    int pos = atomicAdd(&g_cursor[s], 1);
    if (pos < CAP) g_slot[s * CAP + pos] = d | (p << 16);
}

// ---------- phase 3: gather, warp per node, float4 per lane ----------
__global__ void __launch_bounds__(256)
k_gather(const float* __restrict__ x,
         const int*   __restrict__ labels,
         const float* __restrict__ Pb,
         float*       __restrict__ out) {
    int warp = (blockIdx.x * blockDim.x + threadIdx.x) >> 5;   // node id
    int lane = threadIdx.x & 31;
    if (warp >= NN) return;
    int n = warp;

    int lv  = labels[n];                 // uniform per warp (broadcast)
    int cnt = g_cursor[n];
    if (cnt > CAP) cnt = CAP;
    const int*    slots = g_slot + n * CAP;
    const float4* x4    = (const float4*)x;   // row stride = FC/4 = 32 float4

    // acc[k] : one float4 (4 features) per output channel
    float4 a0 = make_float4(0.f, 0.f, 0.f, 0.f);
    float4 a1 = a0, a2 = a0, a3 = a0;

    int lvL = lv * (LC * PC);            // lv*800

    int i = 0;
    for (; i + 1 < cnt; i += 2) {
        int pk0 = slots[i];
        int pk1 = slots[i + 1];
        int d0 = pk0 & 0xFFFF, p0 = pk0 >> 16;
        int d1 = pk1 & 0xFFFF, p1 = pk1 >> 16;
        int lw0 = __ldg(&labels[d0]);
        int lw1 = __ldg(&labels[d1]);
        float4 w0 = g_PwT[lvL + lw0 * PC + p0];   // warp-broadcast
        float4 w1 = g_PwT[lvL + lw1 * PC + p1];
        float4 xv0 = __ldg(&x4[d0 * (FC / 4) + lane]);
        float4 xv1 = __ldg(&x4[d1 * (FC / 4) + lane]);

        a0.x += w0.x * xv0.x; a0.y += w0.x * xv0.y; a0.z += w0.x * xv0.z; a0.w += w0.x * xv0.w;
        a1.x += w0.y * xv0.x; a1.y += w0.y * xv0.y; a1.z += w0.y * xv0.z; a1.w += w0.y * xv0.w;
        a2.x += w0.z * xv0.x; a2.y += w0.z * xv0.y; a2.z += w0.z * xv0.z; a2.w += w0.z * xv0.w;
        a3.x += w0.w * xv0.x; a3.y += w0.w * xv0.y; a3.z += w0.w * xv0.z; a3.w += w0.w * xv0.w;

        a0.x += w1.x * xv1.x; a0.y += w1.x * xv1.y; a0.z += w1.x * xv1.z; a0.w += w1.x * xv1.w;
        a1.x += w1.y * xv1.x; a1.y += w1.y * xv1.y; a1.z += w1.y * xv1.z; a1.w += w1.y * xv1.w;
        a2.x += w1.z * xv1.x; a2.y += w1.z * xv1.y; a2.z += w1.z * xv1.z; a2.w += w1.z * xv1.w;
        a3.x += w1.w * xv1.x; a3.y += w1.w * xv1.y; a3.z += w1.w * xv1.z; a3.w += w1.w * xv1.w;
    }
    if (i < cnt) {
        int pk0 = slots[i];
        int d0 = pk0 & 0xFFFF, p0 = pk0 >> 16;
        int lw0 = __ldg(&labels[d0]);
        float4 w0 = g_PwT[lvL + lw0 * PC + p0];
        float4 xv0 = __ldg(&x4[d0 * (FC / 4) + lane]);
        a0.x += w0.x * xv0.x; a0.y += w0.x * xv0.y; a0.z += w0.x * xv0.z; a0.w += w0.x * xv0.w;
        a1.x += w0.y * xv0.x; a1.y += w0.y * xv0.y; a1.z += w0.y * xv0.z; a1.w += w0.y * xv0.w;
        a2.x += w0.z * xv0.x; a2.y += w0.z * xv0.y; a2.z += w0.z * xv0.z; a2.w += w0.z * xv0.w;
        a3.x += w0.w * xv0.x; a3.y += w0.w * xv0.y; a3.z += w0.w * xv0.z; a3.w += w0.w * xv0.w;
    }

    // Epilogue: bias (k*L + lv)*F + f, out row n*(K*F)
    const float4* pb = (const float4*)Pb;     // index = ((k*LC + lv)*FC)/4 + lane
    float4*       o  = (float4*)(out + (size_t)n * (KC * FC));

    float4 b0 = __ldg(&pb[(0 * LC + lv) * (FC / 4) + lane]);
    float4 b1 = __ldg(&pb[(1 * LC + lv) * (FC / 4) + lane]);
    float4 b2 = __ldg(&pb[(2 * LC + lv) * (FC / 4) + lane]);
    float4 b3 = __ldg(&pb[(3 * LC + lv) * (FC / 4) + lane]);

    a0.x += b0.x; a0.y += b0.y; a0.z += b0.z; a0.w += b0.w;
    a1.x += b1.x; a1.y += b1.y; a1.z += b1.z; a1.w += b1.w;
    a2.x += b2.x; a2.y += b2.y; a2.z += b2.z; a2.w += b2.w;
    a3.x += b3.x; a3.y += b3.y; a3.z += b3.z; a3.w += b3.w;

    o[0 * (FC / 4) + lane] = a0;
    o[1 * (FC / 4) + lane] = a1;
    o[2 * (FC / 4) + lane] = a2;
    o[3 * (FC / 4) + lane] = a3;
}

extern "C" void kernel_launch(void* const* d_in, const int* in_sizes, int n_in,
                              void* d_out, int out_size) {
    const float* x         = (const float*)d_in[0];
    const int*   labels    = (const int*)  d_in[1];
    const int*   edge_src  = (const int*)  d_in[2];
    const int*   edge_dst  = (const int*)  d_in[3];
    const int*   edge_prop = (const int*)  d_in[4];
    const float* Pw        = (const float*)d_in[5];
    const float* Pb        = (const float*)d_in[6];
    float*       out       = (float*)d_out;

    const int E = in_sizes[2];   // 640000
    (void)n_in; (void)out_size;

    k_init<<<(NRULE + 255) / 256, 256>>>(Pw);
    k_scatter<<<(E + 255) / 256, 256>>>(edge_src, edge_dst, edge_prop, E);
    // 20000 warps, 8 nodes per 256-thread block
    k_gather<<<(NN * 32 + 255) / 256, 256>>>(x, labels, Pb, out);
}

// round 4
// speedup vs baseline: 2.1073x; 1.0322x over previous
#include <cuda_runtime.h>
#include <cuda_bf16.h>

// Rule-indexed sparse graph convolution, round 3 (re-bench; infra failure last round).
//   out[n,k,f] = sum_{e: src(e)=n} W[k, lab[src], lab[dst], prop(e)] * x[dst(e), f]
//              + b[k, lab[n], f]
//
// Pipeline:
//  1. k_init    : zero cursors (int4) + transpose Param_W -> float4 PwT (vectorized)
//  2. k_scatter : bucket edges by src; pack (lw*16+p)<<15 | d  (labels[d] gathered HERE)
//  3. k_gather  : warp-per-node, lane = float4 of features, unroll-4 with int4
//                 slot loads; weight lookup is a single warp-broadcast PwT read.

#define KC 4
#define LC 50
#define PC 16
#define FC 128
#define NN 20000
#define EE 640000
#define LLP (LC * LC * PC)    // 40000, k-stride in Param_W
#define NRULE (LC * LC * PC)  // 40000 rules: (lv*L+lw)*P+p
#define CAP 128               // slots/node; Poisson(32) -> overflow prob ~1e-35

// ---------- static scratch (allocation-free) ----------
__device__ int    g_cursor[NN];
__device__ __align__(16) int g_slot[NN * CAP];   // packed (lw*PC+p)<<15 | d
__device__ float4 g_PwT[NRULE];                  // {w_k0,w_k1,w_k2,w_k3} per rule

// ---------- phase 1: zero cursors + transpose weights (vectorized) ----------
__global__ void __launch_bounds__(256)
k_init(const float* __restrict__ Pw) {
    int t = blockIdx.x * blockDim.x + threadIdx.x;   // 0..9999
    if (t < NRULE / 4) {
        const float4* Pw4 = (const float4*)Pw;
        float4 w0 = __ldg(&Pw4[t]);                    // Pw[4t..4t+3], k=0
        float4 w1 = __ldg(&Pw4[t + LLP / 4]);          // k=1
        float4 w2 = __ldg(&Pw4[t + 2 * LLP / 4]);      // k=2
        float4 w3 = __ldg(&Pw4[t + 3 * LLP / 4]);      // k=3
        int b = t * 4;
        g_PwT[b + 0] = make_float4(w0.x, w1.x, w2.x, w3.x);
        g_PwT[b + 1] = make_float4(w0.y, w1.y, w2.y, w3.y);
        g_PwT[b + 2] = make_float4(w0.z, w1.z, w2.z, w3.z);
        g_PwT[b + 3] = make_float4(w0.w, w1.w, w2.w, w3.w);
    }
    if (t < NN / 4) {
        ((int4*)g_cursor)[t] = make_int4(0, 0, 0, 0);
    }
}

// ---------- phase 2: bucket edges by src, pack rule-part + dst ----------
__global__ void __launch_bounds__(256)
k_scatter(const int* __restrict__ edge_src,
          const int* __restrict__ edge_dst,
          const int* __restrict__ edge_prop,
          const int* __restrict__ labels,
          int E) {
    int e = blockIdx.x * blockDim.x + threadIdx.x;
    if (e >= E) return;
    int s  = edge_src[e];
    int d  = edge_dst[e];
    int p  = edge_prop[e];
    int lw = __ldg(&labels[d]);
    int pk = ((lw * PC + p) << 15) | d;        // d < 32768, lw*16+p < 800
    int pos = atomicAdd(&g_cursor[s], 1);
    if (pos < CAP) g_slot[s * CAP + pos] = pk;
}

// ---------- phase 3: gather, warp per node, unroll-4 ----------
__global__ void __launch_bounds__(256)
k_gather(const float* __restrict__ x,
         const int*   __restrict__ labels,
         const float* __restrict__ Pb,
         float*       __restrict__ out) {
    int warp = (blockIdx.x * blockDim.x + threadIdx.x) >> 5;   // node id
    int lane = threadIdx.x & 31;
    if (warp >= NN) return;
    int n = warp;

    int lv  = labels[n];                       // uniform per warp
    int cnt = g_cursor[n];
    if (cnt > CAP) cnt = CAP;
    const int4*   slots4 = (const int4*)(g_slot + n * CAP);    // 16B aligned
    const float4* x4     = (const float4*)x;   // row stride = 32 float4

    float4 a0 = make_float4(0.f, 0.f, 0.f, 0.f);
    float4 a1 = a0, a2 = a0, a3 = a0;

    const float4* PwTlv = g_PwT + lv * (LC * PC);   // + (lw*PC+p)

    int i = 0;
    for (; i + 4 <= cnt; i += 4) {
        int4 pk = slots4[i >> 2];
        int d0 = pk.x & 0x7FFF, r0 = pk.x >> 15;
        int d1 = pk.y & 0x7FFF, r1 = pk.y >> 15;
        int d2 = pk.z & 0x7FFF, r2 = pk.z >> 15;
        int d3 = pk.w & 0x7FFF, r3 = pk.w >> 15;

        float4 w0 = __ldg(&PwTlv[r0]);   // warp-broadcast sectors
        float4 w1 = __ldg(&PwTlv[r1]);
        float4 w2 = __ldg(&PwTlv[r2]);
        float4 w3 = __ldg(&PwTlv[r3]);
        float4 v0 = __ldg(&x4[d0 * (FC / 4) + lane]);
        float4 v1 = __ldg(&x4[d1 * (FC / 4) + lane]);
        float4 v2 = __ldg(&x4[d2 * (FC / 4) + lane]);
        float4 v3 = __ldg(&x4[d3 * (FC / 4) + lane]);

        a0.x += w0.x * v0.x; a0.y += w0.x * v0.y; a0.z += w0.x * v0.z; a0.w += w0.x * v0.w;
        a1.x += w0.y * v0.x; a1.y += w0.y * v0.y; a1.z += w0.y * v0.z; a1.w += w0.y * v0.w;
        a2.x += w0.z * v0.x; a2.y += w0.z * v0.y; a2.z += w0.z * v0.z; a2.w += w0.z * v0.w;
        a3.x += w0.w * v0.x; a3.y += w0.w * v0.y; a3.z += w0.w * v0.z; a3.w += w0.w * v0.w;

        a0.x += w1.x * v1.x; a0.y += w1.x * v1.y; a0.z += w1.x * v1.z; a0.w += w1.x * v1.w;
        a1.x += w1.y * v1.x; a1.y += w1.y * v1.y; a1.z += w1.y * v1.z; a1.w += w1.y * v1.w;
        a2.x += w1.z * v1.x; a2.y += w1.z * v1.y; a2.z += w1.z * v1.z; a2.w += w1.z * v1.w;
        a3.x += w1.w * v1.x; a3.y += w1.w * v1.y; a3.z += w1.w * v1.z; a3.w += w1.w * v1.w;

        a0.x += w2.x * v2.x; a0.y += w2.x * v2.y; a0.z += w2.x * v2.z; a0.w += w2.x * v2.w;
        a1.x += w2.y * v2.x; a1.y += w2.y * v2.y; a1.z += w2.y * v2.z; a1.w += w2.y * v2.w;
        a2.x += w2.z * v2.x; a2.y += w2.z * v2.y; a2.z += w2.z * v2.z; a2.w += w2.z * v2.w;
        a3.x += w2.w * v2.x; a3.y += w2.w * v2.y; a3.z += w2.w * v2.z; a3.w += w2.w * v2.w;

        a0.x += w3.x * v3.x; a0.y += w3.x * v3.y; a0.z += w3.x * v3.z; a0.w += w3.x * v3.w;
        a1.x += w3.y * v3.x; a1.y += w3.y * v3.y; a1.z += w3.y * v3.z; a1.w += w3.y * v3.w;
        a2.x += w3.z * v3.x; a2.y += w3.z * v3.y; a2.z += w3.z * v3.z; a2.w += w3.z * v3.w;
        a3.x += w3.w * v3.x; a3.y += w3.w * v3.y; a3.z += w3.w * v3.z; a3.w += w3.w * v3.w;
    }
    for (; i < cnt; ++i) {
        int pk = g_slot[n * CAP + i];
        int d0 = pk & 0x7FFF, r0 = pk >> 15;
        float4 w0 = __ldg(&PwTlv[r0]);
        float4 v0 = __ldg(&x4[d0 * (FC / 4) + lane]);
        a0.x += w0.x * v0.x; a0.y += w0.x * v0.y; a0.z += w0.x * v0.z; a0.w += w0.x * v0.w;
        a1.x += w0.y * v0.x; a1.y += w0.y * v0.y; a1.z += w0.y * v0.z; a1.w += w0.y * v0.w;
        a2.x += w0.z * v0.x; a2.y += w0.z * v0.y; a2.z += w0.z * v0.z; a2.w += w0.z * v0.w;
        a3.x += w0.w * v0.x; a3.y += w0.w * v0.y; a3.z += w0.w * v0.z; a3.w += w0.w * v0.w;
    }

    // Epilogue: bias + coalesced float4 stores
    const float4* pb = (const float4*)Pb;
    float4*       o  = (float4*)(out + (size_t)n * (KC * FC));

    float4 b0 = __ldg(&pb[(0 * LC + lv) * (FC / 4) + lane]);
    float4 b1 = __ldg(&pb[(1 * LC + lv) * (FC / 4) + lane]);
    float4 b2 = __ldg(&pb[(2 * LC + lv) * (FC / 4) + lane]);
    float4 b3 = __ldg(&pb[(3 * LC + lv) * (FC / 4) + lane]);

    a0.x += b0.x; a0.y += b0.y; a0.z += b0.z; a0.w += b0.w;
    a1.x += b1.x; a1.y += b1.y; a1.z += b1.z; a1.w += b1.w;
    a2.x += b2.x; a2.y += b2.y; a2.z += b2.z; a2.w += b2.w;
    a3.x += b3.x; a3.y += b3.y; a3.z += b3.z; a3.w += b3.w;

    o[0 * (FC / 4) + lane] = a0;
    o[1 * (FC / 4) + lane] = a1;
    o[2 * (FC / 4) + lane] = a2;
    o[3 * (FC / 4) + lane] = a3;
}

extern "C" void kernel_launch(void* const* d_in, const int* in_sizes, int n_in,
                              void* d_out, int out_size) {
    const float* x         = (const float*)d_in[0];
    const int*   labels    = (const int*)  d_in[1];
    const int*   edge_src  = (const int*)  d_in[2];
    const int*   edge_dst  = (const int*)  d_in[3];
    const int*   edge_prop = (const int*)  d_in[4];
    const float* Pw        = (const float*)d_in[5];
    const float* Pb        = (const float*)d_in[6];
    float*       out       = (float*)d_out;

    const int E = in_sizes[2];   // 640000
    (void)n_in; (void)out_size;

    k_init<<<(NRULE / 4 + 255) / 256, 256>>>(Pw);
    k_scatter<<<(E + 255) / 256, 256>>>(edge_src, edge_dst, edge_prop, labels, E);
    k_gather<<<(NN * 32 + 255) / 256, 256>>>(x, labels, Pb, out);
}